// round 6
// baseline (speedup 1.0000x reference)
#include <cuda_runtime.h>
#include <math.h>

#define TT 128
#define NB 256
#define EE 512
#define AD 8
#define HH 512
#define H3 1536
#define TN (TT*NB)
#define TNH ((size_t)TN*HH)
#define NH (NB*HH)
#define NCTA 128

// Scratch (no cudaMalloc allowed)
__device__ float g_gi [(size_t)TN * H3];   // input-side gates, cell 1 (+ b_ih + b_hh[r,z])
__device__ float g_gip[(size_t)TN * H3];   // input-side gates, cell 2
__device__ float g_A [2][2][NH];           // masked hidden state, parity double-buffer

__device__ __forceinline__ unsigned f2tf(float x) {
    unsigned r;
    asm("cvt.rna.tf32.f32 %0, %1;" : "=r"(r) : "f"(x));
    return r;
}

__device__ __forceinline__ void mma8(float* c, const unsigned* a, const unsigned* b) {
    asm volatile(
        "mma.sync.aligned.m16n8k8.row.col.f32.tf32.tf32.f32 "
        "{%0,%1,%2,%3},{%4,%5,%6,%7},{%8,%9},{%0,%1,%2,%3};"
        : "+f"(c[0]), "+f"(c[1]), "+f"(c[2]), "+f"(c[3])
        : "r"(a[0]), "r"(a[1]), "r"(a[2]), "r"(a[3]), "r"(b[0]), "r"(b[1]));
}

__device__ __forceinline__ float fsig(float x) {
    return 1.f / (1.f + __expf(-x));
}
__device__ __forceinline__ float ftanh(float x) {
    return 1.f - 2.f / (__expf(2.f * x) + 1.f);
}

__device__ __forceinline__ float2 ldcg2(const float* p) {
    float2 v;
    asm volatile("ld.global.cg.v2.f32 {%0,%1}, [%2];" : "=f"(v.x), "=f"(v.y) : "l"(p));
    return v;
}

// ===========================================================================
// GI GEMM (unchanged, passing): g_gi/g_gip with biases folded
// ===========================================================================
__global__ void __launch_bounds__(256) gi_gemm_k(
    const float* __restrict__ x,
    const float* __restrict__ wih,  const float* __restrict__ wihp,
    const float* __restrict__ pah,  const float* __restrict__ masks,
    const float* __restrict__ bih,  const float* __restrict__ bihp,
    const float* __restrict__ bhh,  const float* __restrict__ bhhp)
{
    constexpr int BM = 128, BN = 128, BK = 16, SA = 20;
    constexpr int WRM = 2;
    constexpr int MT = 4, NT = 4, AV = 2, BV = 2;

    __shared__ unsigned sA[2][BM * SA];
    __shared__ unsigned sB[2][BN * SA];

    const int m0 = blockIdx.y * BM;
    const int n0 = blockIdx.x * BN;
    const float* Bg = wih + (size_t)n0 * 520;

    const int tid = threadIdx.x, lane = tid & 31, warp = tid >> 5;
    const int wm = warp % WRM, wn = warp / WRM;

    float acc[MT][NT][4];
    float acc2[MT][NT][4];
#pragma unroll
    for (int i = 0; i < MT; i++)
#pragma unroll
        for (int j = 0; j < NT; j++)
#pragma unroll
            for (int q = 0; q < 4; q++) { acc[i][j][q] = 0.f; acc2[i][j][q] = 0.f; }

    unsigned ra[AV][4], rb[BV][4];

    auto GL = [&](int kc) {
#pragma unroll
        for (int i = 0; i < AV; i++) {
            int s = tid + i * 256; int r = s >> 2; int c = (s & 3) << 2;
            float4 v = *reinterpret_cast<const float4*>(x + (size_t)(m0 + r) * EE + kc * BK + c);
            ra[i][0] = f2tf(v.x); ra[i][1] = f2tf(v.y); ra[i][2] = f2tf(v.z); ra[i][3] = f2tf(v.w);
        }
#pragma unroll
        for (int i = 0; i < BV; i++) {
            int s = tid + i * 256; int r = s >> 2; int c = (s & 3) << 2;
            float4 v = *reinterpret_cast<const float4*>(Bg + (size_t)r * 520 + kc * BK + c);
            rb[i][0] = f2tf(v.x); rb[i][1] = f2tf(v.y); rb[i][2] = f2tf(v.z); rb[i][3] = f2tf(v.w);
        }
    };
    auto SS = [&](int buf) {
#pragma unroll
        for (int i = 0; i < AV; i++) {
            int s = tid + i * 256; int r = s >> 2; int c = (s & 3) << 2;
            *reinterpret_cast<uint4*>(&sA[buf][r * SA + c]) = *reinterpret_cast<uint4*>(ra[i]);
        }
#pragma unroll
        for (int i = 0; i < BV; i++) {
            int s = tid + i * 256; int r = s >> 2; int c = (s & 3) << 2;
            *reinterpret_cast<uint4*>(&sB[buf][r * SA + c]) = *reinterpret_cast<uint4*>(rb[i]);
        }
    };
    auto COMP = [&](int buf) {
#pragma unroll
        for (int k8 = 0; k8 < BK / 8; k8++) {
            unsigned af[MT][4]; unsigned bf[NT][2];
#pragma unroll
            for (int mt = 0; mt < MT; mt++) {
                int r = wm * MT * 16 + mt * 16 + (lane >> 2);
                int c = k8 * 8 + (lane & 3);
                af[mt][0] = sA[buf][r * SA + c];
                af[mt][1] = sA[buf][(r + 8) * SA + c];
                af[mt][2] = sA[buf][r * SA + c + 4];
                af[mt][3] = sA[buf][(r + 8) * SA + c + 4];
            }
#pragma unroll
            for (int nt = 0; nt < NT; nt++) {
                int n = wn * NT * 8 + nt * 8 + (lane >> 2);
                int kk = k8 * 8 + (lane & 3);
                bf[nt][0] = sB[buf][n * SA + kk];
                bf[nt][1] = sB[buf][n * SA + kk + 4];
            }
#pragma unroll
            for (int mt = 0; mt < MT; mt++)
#pragma unroll
                for (int nt = 0; nt < NT; nt++)
                    mma8(acc[mt][nt], af[mt], bf[nt]);
        }
    };

    GL(0); SS(0); __syncthreads();
    constexpr int NKC = EE / BK;
    for (int kc = 0; kc < NKC; kc++) {
        if (kc + 1 < NKC) GL(kc + 1);
        COMP(kc & 1);
        if (kc + 1 < NKC) SS((kc + 1) & 1);
        __syncthreads();
    }

    // Tail: masked prev-action (K=8)
    {
        int s = tid;
        if (s < BM * 2) {
            int r = s >> 1; int c = (s & 1) << 2;
            float4 v = *reinterpret_cast<const float4*>(pah + (size_t)(m0 + r) * AD + c);
            float mk = masks[m0 + r];
            uint4 t4 = { f2tf(v.x * mk), f2tf(v.y * mk), f2tf(v.z * mk), f2tf(v.w * mk) };
            *reinterpret_cast<uint4*>(&sA[0][r * SA + c]) = t4;
        }
        if (s < BN * 2) {
            int n = s >> 1; int c = (s & 1) << 2;
            float4 v = *reinterpret_cast<const float4*>(wih + (size_t)(n0 + n) * 520 + 512 + c);
            uint4 t4 = { f2tf(v.x), f2tf(v.y), f2tf(v.z), f2tf(v.w) };
            *reinterpret_cast<uint4*>(&sB[0][n * SA + c]) = t4;
            float4 w = *reinterpret_cast<const float4*>(wihp + (size_t)(n0 + n) * AD + c);
            uint4 t5 = { f2tf(w.x), f2tf(w.y), f2tf(w.z), f2tf(w.w) };
            *reinterpret_cast<uint4*>(&sB[1][n * SA + c]) = t5;
        }
    }
    __syncthreads();
    {
        unsigned af2[MT][4], b0f[NT][2], b1f[NT][2];
#pragma unroll
        for (int mt = 0; mt < MT; mt++) {
            int r = wm * MT * 16 + mt * 16 + (lane >> 2);
            int c = (lane & 3);
            af2[mt][0] = sA[0][r * SA + c];
            af2[mt][1] = sA[0][(r + 8) * SA + c];
            af2[mt][2] = sA[0][r * SA + c + 4];
            af2[mt][3] = sA[0][(r + 8) * SA + c + 4];
        }
#pragma unroll
        for (int nt = 0; nt < NT; nt++) {
            int n = wn * NT * 8 + nt * 8 + (lane >> 2);
            int kk = (lane & 3);
            b0f[nt][0] = sB[0][n * SA + kk]; b0f[nt][1] = sB[0][n * SA + kk + 4];
            b1f[nt][0] = sB[1][n * SA + kk]; b1f[nt][1] = sB[1][n * SA + kk + 4];
        }
#pragma unroll
        for (int mt = 0; mt < MT; mt++)
#pragma unroll
            for (int nt = 0; nt < NT; nt++) {
                mma8(acc[mt][nt], af2[mt], b0f[nt]);
                mma8(acc2[mt][nt], af2[mt], b1f[nt]);
            }
    }

#pragma unroll
    for (int mt = 0; mt < MT; mt++)
#pragma unroll
        for (int nt = 0; nt < NT; nt++) {
            int r = m0 + wm * MT * 16 + mt * 16 + (lane >> 2);
            int c = n0 + wn * NT * 8 + nt * 8 + ((lane & 3) << 1);
            float hb0 = (c < 1024) ? bhh[c] : 0.f;
            float hb1 = (c < 1024) ? bhh[c + 1] : 0.f;
            float b0 = bih[c] + hb0, b1 = bih[c + 1] + hb1;
            *reinterpret_cast<float2*>(&g_gi[(size_t)r * H3 + c]) =
                make_float2(acc[mt][nt][0] + b0, acc[mt][nt][1] + b1);
            *reinterpret_cast<float2*>(&g_gi[(size_t)(r + 8) * H3 + c]) =
                make_float2(acc[mt][nt][2] + b0, acc[mt][nt][3] + b1);
            float pb0 = (c < 1024) ? bhhp[c] : 0.f;
            float pb1 = (c < 1024) ? bhhp[c + 1] : 0.f;
            float p0 = bihp[c] + pb0, p1 = bihp[c + 1] + pb1;
            *reinterpret_cast<float2*>(&g_gip[(size_t)r * H3 + c]) =
                make_float2(acc2[mt][nt][0] + p0, acc2[mt][nt][1] + p1);
            *reinterpret_cast<float2*>(&g_gip[(size_t)(r + 8) * H3 + c]) =
                make_float2(acc2[mt][nt][2] + p0, acc2[mt][nt][3] + p1);
        }
}

// ===========================================================================
// Persistent scan. 128 CTAs x 128 threads, 8 clusters of 16 (one per
// (m-tile, cell) group). HW cluster barrier between steps. Own j-slice of
// the next state is STS'd directly into stage 0; h carried in registers.
// ===========================================================================
#define SW_LD 516
#define SA_LD 36
#define SMEM_SCAN ((96*SW_LD + 3*64*SA_LD) * 4)

__global__ void __launch_bounds__(128, 1) __cluster_dims__(16, 1, 1) scan_k(
    const float* __restrict__ whh, const float* __restrict__ whhp,
    const float* __restrict__ masks, const float* __restrict__ ginit,
    const float* __restrict__ bhh, const float* __restrict__ bhhp,
    const float* __restrict__ hxs, const float* __restrict__ hys,
    float* __restrict__ out)
{
    extern __shared__ unsigned sh[];
    unsigned* sW = sh;                      // 96 x 516 (weights, tf32)
    unsigned* sA = sh + 96 * SW_LD;         // 3 stages x 64 x 36 (A chunks)

    const int bx = blockIdx.x;
    const int p  = bx & 15;                 // cluster rank == j-slice
    const int j0 = p * 32;
    const int m0 = ((bx >> 4) & 3) * 64;
    const int cell = bx >> 6;

    const float* W  = cell ? whhp : whh;
    const float* gi = cell ? g_gip : g_gi;
    const float* bh = cell ? bhhp : bhh;
    float* outs = out + (cell ? (TNH + NH) : 0);
    float* hf   = out + (cell ? (2 * TNH + NH) : TNH);

    const int tid = threadIdx.x, lane = tid & 31, warp = tid >> 5;
    const int wm = warp & 1, wn = warp >> 1;

    // ---- preload weights into SMEM (tf32, RNA) ----
    for (int i = tid; i < 96 * 128; i += 128) {
        int rr = i >> 7, cc = (i & 127) << 2;
        int g = rr >> 5, jj = rr & 31;
        float4 v = *reinterpret_cast<const float4*>(W + (size_t)(g * HH + j0 + jj) * HH + cc);
        unsigned* d = &sW[rr * SW_LD + cc];
        d[0] = f2tf(v.x); d[1] = f2tf(v.y); d[2] = f2tf(v.z); d[3] = f2tf(v.w);
    }

    // ---- init own slice of A[cell][0]: global + stage0 SMEM ----
    {
        const float* hsrc = cell ? hys : hxs;
        for (int idx = tid; idx < 64 * 32; idx += 128) {
            int row = idx >> 5, col = idx & 31;
            int n = m0 + row, c = j0 + col;
            float mk = masks[n];
            float v = hsrc[(size_t)n * HH + c] * mk;
            if (cell) v += ginit[(size_t)n * HH + c] * (1.f - mk);
            g_A[cell][0][(size_t)n * HH + c] = v;
            sA[row * SA_LD + col] = __float_as_uint(v);
        }
    }

    const int cb = j0 + wn * 16 + ((lane & 3) << 1);
    float2 bn2[2];
    bn2[0] = *reinterpret_cast<const float2*>(bh + 2 * HH + cb);
    bn2[1] = *reinterpret_cast<const float2*>(bh + 2 * HH + cb + 8);

    unsigned sA_u32;
    asm("{ .reg .u64 t; cvta.to.shared.u64 t, %1; cvt.u32.u64 %0, t; }"
        : "=r"(sA_u32) : "l"(sA));

    // publish init to cluster peers
    asm volatile("barrier.cluster.arrive.aligned;" ::: "memory");
    asm volatile("barrier.cluster.wait.aligned;" ::: "memory");

    float2 hq[4][2];   // register-carried A(t)[n, cb..] for this thread's cells

    for (int t = 0; t < TT; t++) {
        const int rb = t & 1;
        const float* Ard = g_A[cell][rb];
        float*       Awr = g_A[cell][rb ^ 1];
        const size_t trow = (size_t)t * NB;
        const float* As = Ard + (size_t)m0 * HH;

        auto issue = [&](int chunk, int stg) {
#pragma unroll
            for (int pp = 0; pp < 4; pp++) {
                int s = tid + pp * 128;
                int row = s >> 3;
                int c4 = (s & 7) << 2;
                unsigned d = sA_u32 + ((((stg * 64) + row) * SA_LD + c4) << 2);
                const float* src = As + (size_t)row * HH + chunk * 32 + c4;
                asm volatile("cp.async.cg.shared.global [%0], [%1], 16;" :: "r"(d), "l"(src));
            }
        };

        // prologue: chunk p is already in stage 0 (STS); load p+1 now
        issue((p + 1) & 15, 1); asm volatile("cp.async.commit_group;");

        // ---- epilogue operand prefetch (overlaps the GEMM) ----
        float2 pir[4][2], piz[4][2], pin[4][2], pg[4][2];
        float pmask[4];
#pragma unroll
        for (int q = 0; q < 4; q++) {
            int n = m0 + wm * 32 + (q >> 1) * 16 + (lane >> 2) + (q & 1) * 8;
            size_t gb = (trow + n) * (size_t)H3 + cb;
            pmask[q] = (t < TT - 1) ? masks[trow + NB + n] : 0.f;
#pragma unroll
            for (int nt = 0; nt < 2; nt++) {
                pir[q][nt] = *reinterpret_cast<const float2*>(gi + gb + nt * 8);
                piz[q][nt] = *reinterpret_cast<const float2*>(gi + gb + HH + nt * 8);
                pin[q][nt] = *reinterpret_cast<const float2*>(gi + gb + 2 * HH + nt * 8);
                if (t == 0)
                    hq[q][nt] = ldcg2(Ard + (size_t)n * HH + cb + nt * 8);
                if (cell && t < TT - 1)
                    pg[q][nt] = *reinterpret_cast<const float2*>(
                        ginit + (trow + NB + n) * (size_t)HH + cb + nt * 8);
                else
                    pg[q][nt] = make_float2(0.f, 0.f);
            }
        }

        issue((p + 2) & 15, 2); asm volatile("cp.async.commit_group;");

        float acc[3][2][2][4];
#pragma unroll
        for (int g = 0; g < 3; g++)
#pragma unroll
            for (int mt = 0; mt < 2; mt++)
#pragma unroll
                for (int nt = 0; nt < 2; nt++)
#pragma unroll
                    for (int q = 0; q < 4; q++) acc[g][mt][nt][q] = 0.f;

        for (int i = 0; i < 16; i++) {
            const int chunk = (p + i) & 15;
            const int sr = i - (i >= 3 ? 3 : 0) - (i >= 6 ? 3 : 0)
                             - (i >= 9 ? 3 : 0) - (i >= 12 ? 3 : 0) - (i >= 15 ? 3 : 0);
            if (i > 0) {
                if (i < 15) asm volatile("cp.async.wait_group 1;");
                else        asm volatile("cp.async.wait_group 0;");
                __syncthreads();
                if (i <= 13) {
                    int sw = sr + 2; if (sw >= 3) sw -= 3;
                    issue((p + i + 2) & 15, sw);
                    asm volatile("cp.async.commit_group;");
                }
            }
            const unsigned* sab = sA + sr * 64 * SA_LD;
#pragma unroll
            for (int k8 = 0; k8 < 4; k8++) {
                const int ck = k8 * 8 + (lane & 3);
                unsigned af[2][4];
#pragma unroll
                for (int mt = 0; mt < 2; mt++) {
                    int r = wm * 32 + mt * 16 + (lane >> 2);
                    af[mt][0] = sab[r * SA_LD + ck];
                    af[mt][1] = sab[(r + 8) * SA_LD + ck];
                    af[mt][2] = sab[r * SA_LD + ck + 4];
                    af[mt][3] = sab[(r + 8) * SA_LD + ck + 4];
                }
                const int kg = chunk * 32 + ck;
#pragma unroll
                for (int g = 0; g < 3; g++)
#pragma unroll
                    for (int nt = 0; nt < 2; nt++) {
                        int bn = g * 32 + wn * 16 + nt * 8 + (lane >> 2);
                        unsigned bf[2] = { sW[bn * SW_LD + kg], sW[bn * SW_LD + kg + 4] };
#pragma unroll
                        for (int mt = 0; mt < 2; mt++)
                            mma8(acc[g][mt][nt], af[mt], bf);
                    }
            }
        }

        // stage 0 is re-written below (own next chunk) — all readers must finish
        if (t < TT - 1) __syncthreads();

        // ---- fused gate epilogue ----
#pragma unroll
        for (int mt = 0; mt < 2; mt++)
#pragma unroll
            for (int half = 0; half < 2; half++) {
                int q = mt * 2 + half;
                int n = m0 + wm * 32 + mt * 16 + (lane >> 2) + half * 8;
                size_t mrow = trow + n;
                float mnx = pmask[q];
#pragma unroll
                for (int nt = 0; nt < 2; nt++) {
                    int c = cb + nt * 8;
                    float rr0 = fsig(pir[q][nt].x + acc[0][mt][nt][half * 2]);
                    float rr1 = fsig(pir[q][nt].y + acc[0][mt][nt][half * 2 + 1]);
                    float zz0 = fsig(piz[q][nt].x + acc[1][mt][nt][half * 2]);
                    float zz1 = fsig(piz[q][nt].y + acc[1][mt][nt][half * 2 + 1]);
                    float nn0 = ftanh(pin[q][nt].x + rr0 * (acc[2][mt][nt][half * 2] + bn2[nt].x));
                    float nn1 = ftanh(pin[q][nt].y + rr1 * (acc[2][mt][nt][half * 2 + 1] + bn2[nt].y));
                    float h0 = (1.f - zz0) * nn0 + zz0 * hq[q][nt].x;
                    float h1 = (1.f - zz1) * nn1 + zz1 * hq[q][nt].y;
                    *reinterpret_cast<float2*>(outs + mrow * HH + c) = make_float2(h0, h1);
                    if (t == TT - 1) {
                        *reinterpret_cast<float2*>(hf + (size_t)n * HH + c) = make_float2(h0, h1);
                    } else {
                        float a0 = h0 * mnx + pg[q][nt].x * (1.f - mnx);
                        float a1 = h1 * mnx + pg[q][nt].y * (1.f - mnx);
                        *reinterpret_cast<float2*>(Awr + (size_t)n * HH + c) = make_float2(a0, a1);
                        hq[q][nt] = make_float2(a0, a1);
                        // own next-step chunk straight into stage 0
                        unsigned ad = sA_u32 +
                            (((wm * 32 + mt * 16 + (lane >> 2) + half * 8) * SA_LD
                              + wn * 16 + nt * 8 + ((lane & 3) << 1)) << 2);
                        asm volatile("st.shared.v2.f32 [%0], {%1,%2};"
                                     :: "r"(ad), "f"(a0), "f"(a1));
                    }
                }
            }

        if (t < TT - 1) {
            asm volatile("barrier.cluster.arrive.aligned;" ::: "memory");
            asm volatile("barrier.cluster.wait.aligned;" ::: "memory");
        }
    }
}

extern "C" void kernel_launch(void* const* d_in, const int* in_sizes, int n_in,
                              void* d_out, int out_size)
{
    const float* x     = (const float*)d_in[0];
    const float* hxs   = (const float*)d_in[1];
    const float* hys   = (const float*)d_in[2];
    const float* ginit = (const float*)d_in[3];
    const float* masks = (const float*)d_in[4];
    const float* pah   = (const float*)d_in[5];
    const float* wih   = (const float*)d_in[6];
    const float* whh   = (const float*)d_in[7];
    const float* bih   = (const float*)d_in[8];
    const float* bhh   = (const float*)d_in[9];
    const float* wihp  = (const float*)d_in[10];
    const float* whhp  = (const float*)d_in[11];
    const float* bihp  = (const float*)d_in[12];
    const float* bhhp  = (const float*)d_in[13];
    float* out = (float*)d_out;

    cudaFuncSetAttribute(scan_k, cudaFuncAttributeMaxDynamicSharedMemorySize, SMEM_SCAN);
    cudaFuncSetAttribute(scan_k, cudaFuncAttributeNonPortableClusterSizeAllowed, 1);

    gi_gemm_k<<<dim3(12, 256), 256>>>(x, wih, wihp, pah, masks, bih, bihp, bhh, bhhp);

    scan_k<<<NCTA, 128, SMEM_SCAN>>>(whh, whhp, masks, ginit, bhh, bhhp, hxs, hys, out);
}

// round 7
// speedup vs baseline: 1.6589x; 1.6589x over previous
#include <cuda_runtime.h>
#include <math.h>

#define TT 128
#define NB 256
#define EE 512
#define AD 8
#define HH 512
#define H3 1536
#define TN (TT*NB)
#define TNH ((size_t)TN*HH)
#define NH (NB*HH)
#define NCTA 128
#define NGROUP 8
#define GSIZE 16

// Scratch (no cudaMalloc allowed)
__device__ float g_gi [(size_t)TN * H3];   // input-side gates, cell 1 (+ b_ih + b_hh[r,z])
__device__ float g_gip[(size_t)TN * H3];   // input-side gates, cell 2
__device__ float g_A [2][2][NH];           // masked hidden state, parity double-buffer
struct __align__(128) Bar { unsigned cnt; unsigned gen; unsigned pad[30]; };
__device__ Bar g_bars[NGROUP];

__device__ __forceinline__ unsigned f2tf(float x) {
    unsigned r;
    asm("cvt.rna.tf32.f32 %0, %1;" : "=r"(r) : "f"(x));
    return r;
}

__device__ __forceinline__ void mma8(float* c, const unsigned* a, const unsigned* b) {
    asm volatile(
        "mma.sync.aligned.m16n8k8.row.col.f32.tf32.tf32.f32 "
        "{%0,%1,%2,%3},{%4,%5,%6,%7},{%8,%9},{%0,%1,%2,%3};"
        : "+f"(c[0]), "+f"(c[1]), "+f"(c[2]), "+f"(c[3])
        : "r"(a[0]), "r"(a[1]), "r"(a[2]), "r"(a[3]), "r"(b[0]), "r"(b[1]));
}

__device__ __forceinline__ float fsig(float x) {
    return 1.f / (1.f + __expf(-x));
}
__device__ __forceinline__ float ftanh(float x) {
    return 1.f - 2.f / (__expf(2.f * x) + 1.f);
}

// ===========================================================================
// GI GEMM (unchanged, passing): g_gi/g_gip with biases folded
// ===========================================================================
__global__ void __launch_bounds__(256) gi_gemm_k(
    const float* __restrict__ x,
    const float* __restrict__ wih,  const float* __restrict__ wihp,
    const float* __restrict__ pah,  const float* __restrict__ masks,
    const float* __restrict__ bih,  const float* __restrict__ bihp,
    const float* __restrict__ bhh,  const float* __restrict__ bhhp)
{
    constexpr int BM = 128, BN = 128, BK = 16, SA = 20;
    constexpr int WRM = 2;
    constexpr int MT = 4, NT = 4, AV = 2, BV = 2;

    __shared__ unsigned sA[2][BM * SA];
    __shared__ unsigned sB[2][BN * SA];

    const int m0 = blockIdx.y * BM;
    const int n0 = blockIdx.x * BN;
    const float* Bg = wih + (size_t)n0 * 520;

    const int tid = threadIdx.x, lane = tid & 31, warp = tid >> 5;
    const int wm = warp % WRM, wn = warp / WRM;

    float acc[MT][NT][4];
    float acc2[MT][NT][4];
#pragma unroll
    for (int i = 0; i < MT; i++)
#pragma unroll
        for (int j = 0; j < NT; j++)
#pragma unroll
            for (int q = 0; q < 4; q++) { acc[i][j][q] = 0.f; acc2[i][j][q] = 0.f; }

    unsigned ra[AV][4], rb[BV][4];

    auto GL = [&](int kc) {
#pragma unroll
        for (int i = 0; i < AV; i++) {
            int s = tid + i * 256; int r = s >> 2; int c = (s & 3) << 2;
            float4 v = *reinterpret_cast<const float4*>(x + (size_t)(m0 + r) * EE + kc * BK + c);
            ra[i][0] = f2tf(v.x); ra[i][1] = f2tf(v.y); ra[i][2] = f2tf(v.z); ra[i][3] = f2tf(v.w);
        }
#pragma unroll
        for (int i = 0; i < BV; i++) {
            int s = tid + i * 256; int r = s >> 2; int c = (s & 3) << 2;
            float4 v = *reinterpret_cast<const float4*>(Bg + (size_t)r * 520 + kc * BK + c);
            rb[i][0] = f2tf(v.x); rb[i][1] = f2tf(v.y); rb[i][2] = f2tf(v.z); rb[i][3] = f2tf(v.w);
        }
    };
    auto SS = [&](int buf) {
#pragma unroll
        for (int i = 0; i < AV; i++) {
            int s = tid + i * 256; int r = s >> 2; int c = (s & 3) << 2;
            *reinterpret_cast<uint4*>(&sA[buf][r * SA + c]) = *reinterpret_cast<uint4*>(ra[i]);
        }
#pragma unroll
        for (int i = 0; i < BV; i++) {
            int s = tid + i * 256; int r = s >> 2; int c = (s & 3) << 2;
            *reinterpret_cast<uint4*>(&sB[buf][r * SA + c]) = *reinterpret_cast<uint4*>(rb[i]);
        }
    };
    auto COMP = [&](int buf) {
#pragma unroll
        for (int k8 = 0; k8 < BK / 8; k8++) {
            unsigned af[MT][4]; unsigned bf[NT][2];
#pragma unroll
            for (int mt = 0; mt < MT; mt++) {
                int r = wm * MT * 16 + mt * 16 + (lane >> 2);
                int c = k8 * 8 + (lane & 3);
                af[mt][0] = sA[buf][r * SA + c];
                af[mt][1] = sA[buf][(r + 8) * SA + c];
                af[mt][2] = sA[buf][r * SA + c + 4];
                af[mt][3] = sA[buf][(r + 8) * SA + c + 4];
            }
#pragma unroll
            for (int nt = 0; nt < NT; nt++) {
                int n = wn * NT * 8 + nt * 8 + (lane >> 2);
                int kk = k8 * 8 + (lane & 3);
                bf[nt][0] = sB[buf][n * SA + kk];
                bf[nt][1] = sB[buf][n * SA + kk + 4];
            }
#pragma unroll
            for (int mt = 0; mt < MT; mt++)
#pragma unroll
                for (int nt = 0; nt < NT; nt++)
                    mma8(acc[mt][nt], af[mt], bf[nt]);
        }
    };

    GL(0); SS(0); __syncthreads();
    constexpr int NKC = EE / BK;
    for (int kc = 0; kc < NKC; kc++) {
        if (kc + 1 < NKC) GL(kc + 1);
        COMP(kc & 1);
        if (kc + 1 < NKC) SS((kc + 1) & 1);
        __syncthreads();
    }

    // Tail: masked prev-action (K=8)
    {
        int s = tid;
        if (s < BM * 2) {
            int r = s >> 1; int c = (s & 1) << 2;
            float4 v = *reinterpret_cast<const float4*>(pah + (size_t)(m0 + r) * AD + c);
            float mk = masks[m0 + r];
            uint4 t4 = { f2tf(v.x * mk), f2tf(v.y * mk), f2tf(v.z * mk), f2tf(v.w * mk) };
            *reinterpret_cast<uint4*>(&sA[0][r * SA + c]) = t4;
        }
        if (s < BN * 2) {
            int n = s >> 1; int c = (s & 1) << 2;
            float4 v = *reinterpret_cast<const float4*>(wih + (size_t)(n0 + n) * 520 + 512 + c);
            uint4 t4 = { f2tf(v.x), f2tf(v.y), f2tf(v.z), f2tf(v.w) };
            *reinterpret_cast<uint4*>(&sB[0][n * SA + c]) = t4;
            float4 w = *reinterpret_cast<const float4*>(wihp + (size_t)(n0 + n) * AD + c);
            uint4 t5 = { f2tf(w.x), f2tf(w.y), f2tf(w.z), f2tf(w.w) };
            *reinterpret_cast<uint4*>(&sB[1][n * SA + c]) = t5;
        }
    }
    __syncthreads();
    {
        unsigned af2[MT][4], b0f[NT][2], b1f[NT][2];
#pragma unroll
        for (int mt = 0; mt < MT; mt++) {
            int r = wm * MT * 16 + mt * 16 + (lane >> 2);
            int c = (lane & 3);
            af2[mt][0] = sA[0][r * SA + c];
            af2[mt][1] = sA[0][(r + 8) * SA + c];
            af2[mt][2] = sA[0][r * SA + c + 4];
            af2[mt][3] = sA[0][(r + 8) * SA + c + 4];
        }
#pragma unroll
        for (int nt = 0; nt < NT; nt++) {
            int n = wn * NT * 8 + nt * 8 + (lane >> 2);
            int kk = (lane & 3);
            b0f[nt][0] = sB[0][n * SA + kk]; b0f[nt][1] = sB[0][n * SA + kk + 4];
            b1f[nt][0] = sB[1][n * SA + kk]; b1f[nt][1] = sB[1][n * SA + kk + 4];
        }
#pragma unroll
        for (int mt = 0; mt < MT; mt++)
#pragma unroll
            for (int nt = 0; nt < NT; nt++) {
                mma8(acc[mt][nt], af2[mt], b0f[nt]);
                mma8(acc2[mt][nt], af2[mt], b1f[nt]);
            }
    }

#pragma unroll
    for (int mt = 0; mt < MT; mt++)
#pragma unroll
        for (int nt = 0; nt < NT; nt++) {
            int r = m0 + wm * MT * 16 + mt * 16 + (lane >> 2);
            int c = n0 + wn * NT * 8 + nt * 8 + ((lane & 3) << 1);
            float hb0 = (c < 1024) ? bhh[c] : 0.f;
            float hb1 = (c < 1024) ? bhh[c + 1] : 0.f;
            float b0 = bih[c] + hb0, b1 = bih[c + 1] + hb1;
            *reinterpret_cast<float2*>(&g_gi[(size_t)r * H3 + c]) =
                make_float2(acc[mt][nt][0] + b0, acc[mt][nt][1] + b1);
            *reinterpret_cast<float2*>(&g_gi[(size_t)(r + 8) * H3 + c]) =
                make_float2(acc[mt][nt][2] + b0, acc[mt][nt][3] + b1);
            float pb0 = (c < 1024) ? bhhp[c] : 0.f;
            float pb1 = (c < 1024) ? bhhp[c + 1] : 0.f;
            float p0 = bihp[c] + pb0, p1 = bihp[c + 1] + pb1;
            *reinterpret_cast<float2*>(&g_gip[(size_t)r * H3 + c]) =
                make_float2(acc2[mt][nt][0] + p0, acc2[mt][nt][1] + p1);
            *reinterpret_cast<float2*>(&g_gip[(size_t)(r + 8) * H3 + c]) =
                make_float2(acc2[mt][nt][2] + p0, acc2[mt][nt][3] + p1);
        }
}

// ===========================================================================
// Persistent scan. 128 CTAs x 128 threads, 1 CTA/SM, plain grid.
// One atomic group barrier (16 CTAs) per step, with outs stores + next-step
// operand prefetch hidden in the barrier shadow. Own j-slice STS'd into
// stage 0 for the next step; h carried in registers.
// ===========================================================================
#define SW_LD 516
#define SA_LD 36
#define SMEM_SCAN ((96*SW_LD + 3*64*SA_LD) * 4)

__global__ void __launch_bounds__(128, 1) scan_k(
    const float* __restrict__ whh, const float* __restrict__ whhp,
    const float* __restrict__ masks, const float* __restrict__ ginit,
    const float* __restrict__ bhh, const float* __restrict__ bhhp,
    const float* __restrict__ hxs, const float* __restrict__ hys,
    float* __restrict__ out)
{
    extern __shared__ unsigned sh[];
    unsigned* sW = sh;                      // 96 x 516 (weights, tf32)
    unsigned* sA = sh + 96 * SW_LD;         // 3 stages x 64 x 36 (A chunks)

    const int bx = blockIdx.x;
    const int p  = bx & 15;                 // j-slice index
    const int j0 = p * 32;
    const int m0 = ((bx >> 4) & 3) * 64;
    const int cell = bx >> 6;
    const int grp = bx >> 4;                // (m,cell) group of 16 CTAs

    const float* W  = cell ? whhp : whh;
    const float* gi = cell ? g_gip : g_gi;
    const float* bh = cell ? bhhp : bhh;
    float* outs = out + (cell ? (TNH + NH) : 0);
    float* hf   = out + (cell ? (2 * TNH + NH) : TNH);
    unsigned* bcnt = &g_bars[grp].cnt;
    unsigned* bgen = &g_bars[grp].gen;

    const int tid = threadIdx.x, lane = tid & 31, warp = tid >> 5;
    const int wm = warp & 1, wn = warp >> 1;

    // ---- preload weights into SMEM (tf32, RNA) ----
    for (int i = tid; i < 96 * 128; i += 128) {
        int rr = i >> 7, cc = (i & 127) << 2;
        int g = rr >> 5, jj = rr & 31;
        float4 v = *reinterpret_cast<const float4*>(W + (size_t)(g * HH + j0 + jj) * HH + cc);
        unsigned* d = &sW[rr * SW_LD + cc];
        d[0] = f2tf(v.x); d[1] = f2tf(v.y); d[2] = f2tf(v.z); d[3] = f2tf(v.w);
    }

    // ---- init own slice of A(0): global + stage0 SMEM ----
    {
        const float* hsrc = cell ? hys : hxs;
        for (int idx = tid; idx < 64 * 32; idx += 128) {
            int row = idx >> 5, col = idx & 31;
            int n = m0 + row, c = j0 + col;
            float mk = masks[n];
            float v = hsrc[(size_t)n * HH + c] * mk;
            if (cell) v += ginit[(size_t)n * HH + c] * (1.f - mk);
            g_A[cell][0][(size_t)n * HH + c] = v;
            sA[row * SA_LD + col] = __float_as_uint(v);
        }
    }

    const int cb = j0 + wn * 16 + ((lane & 3) << 1);
    float2 bn2[2];
    bn2[0] = *reinterpret_cast<const float2*>(bh + 2 * HH + cb);
    bn2[1] = *reinterpret_cast<const float2*>(bh + 2 * HH + cb + 8);

    unsigned sA_u32;
    asm("{ .reg .u64 t; cvta.to.shared.u64 t, %1; cvt.u32.u64 %0, t; }"
        : "=r"(sA_u32) : "l"(sA));

    // ---- init barrier (publish A(0) slices) ----
    {
        __syncthreads();
        if (tid == 0) {
            __threadfence();
            unsigned g0;
            asm volatile("ld.acquire.gpu.u32 %0, [%1];" : "=r"(g0) : "l"(bgen));
            unsigned v = atomicAdd(bcnt, 1u);
            if (v == GSIZE - 1) {
                *bcnt = 0u;
                asm volatile("st.release.gpu.u32 [%0], %1;" :: "l"(bgen), "r"(g0 + 1u));
            } else {
                unsigned cur;
                do { asm volatile("ld.acquire.gpu.u32 %0, [%1];" : "=r"(cur) : "l"(bgen)); }
                while (cur < g0 + 1u);
            }
        }
        __syncthreads();
    }

    // ---- register-carried state hq = A(0) fragment (read from own stage0) ----
    float2 hq[4][2];
#pragma unroll
    for (int q = 0; q < 4; q++) {
        int row = wm * 32 + (q >> 1) * 16 + (lane >> 2) + (q & 1) * 8;
#pragma unroll
        for (int nt = 0; nt < 2; nt++) {
            int col = wn * 16 + nt * 8 + ((lane & 3) << 1);
            hq[q][nt] = *reinterpret_cast<const float2*>(
                reinterpret_cast<const float*>(sA) + row * SA_LD + col);
        }
    }

    // ---- initial operand prefetch: gi(0), masks(1), ginit(1) ----
    float2 pir[4][2], piz[4][2], pin[4][2], pg[4][2];
    float pmask[4];
#pragma unroll
    for (int q = 0; q < 4; q++) {
        int n = m0 + wm * 32 + (q >> 1) * 16 + (lane >> 2) + (q & 1) * 8;
        size_t gb = (size_t)n * H3 + cb;
        pmask[q] = masks[NB + n];
#pragma unroll
        for (int nt = 0; nt < 2; nt++) {
            pir[q][nt] = *reinterpret_cast<const float2*>(gi + gb + nt * 8);
            piz[q][nt] = *reinterpret_cast<const float2*>(gi + gb + HH + nt * 8);
            pin[q][nt] = *reinterpret_cast<const float2*>(gi + gb + 2 * HH + nt * 8);
            pg[q][nt] = cell ? *reinterpret_cast<const float2*>(
                                   ginit + (size_t)(NB + n) * HH + cb + nt * 8)
                             : make_float2(0.f, 0.f);
        }
    }

    for (int t = 0; t < TT; t++) {
        const int rb = t & 1;
        const float* Ard = g_A[cell][rb];
        float*       Awr = g_A[cell][rb ^ 1];
        const size_t trow = (size_t)t * NB;
        const float* As = Ard + (size_t)m0 * HH;

        auto issue = [&](int chunk, int stg) {
#pragma unroll
            for (int pp = 0; pp < 4; pp++) {
                int s = tid + pp * 128;
                int row = s >> 3;
                int c4 = (s & 7) << 2;
                unsigned d = sA_u32 + ((((stg * 64) + row) * SA_LD + c4) << 2);
                const float* src = As + (size_t)row * HH + chunk * 32 + c4;
                asm volatile("cp.async.cg.shared.global [%0], [%1], 16;" :: "r"(d), "l"(src));
            }
        };

        // chunk p already in stage 0 (STS from previous epilogue / init)
        issue((p + 1) & 15, 1); asm volatile("cp.async.commit_group;");
        issue((p + 2) & 15, 2); asm volatile("cp.async.commit_group;");

        float acc[3][2][2][4];
#pragma unroll
        for (int g = 0; g < 3; g++)
#pragma unroll
            for (int mt = 0; mt < 2; mt++)
#pragma unroll
                for (int nt = 0; nt < 2; nt++)
#pragma unroll
                    for (int q = 0; q < 4; q++) acc[g][mt][nt][q] = 0.f;

        int sr = 0;
        for (int i = 0; i < 16; i++) {
            const int chunk = (p + i) & 15;
            if (i > 0) {
                if (i < 15) asm volatile("cp.async.wait_group 1;");
                else        asm volatile("cp.async.wait_group 0;");
                __syncthreads();
                if (i <= 13) {
                    int sw = sr + 2; if (sw >= 3) sw -= 3;
                    issue((p + i + 2) & 15, sw);
                    asm volatile("cp.async.commit_group;");
                }
            }
            const unsigned* sab = sA + sr * 64 * SA_LD;
#pragma unroll
            for (int k8 = 0; k8 < 4; k8++) {
                const int ck = k8 * 8 + (lane & 3);
                unsigned af[2][4];
#pragma unroll
                for (int mt = 0; mt < 2; mt++) {
                    int r = wm * 32 + mt * 16 + (lane >> 2);
                    af[mt][0] = sab[r * SA_LD + ck];
                    af[mt][1] = sab[(r + 8) * SA_LD + ck];
                    af[mt][2] = sab[r * SA_LD + ck + 4];
                    af[mt][3] = sab[(r + 8) * SA_LD + ck + 4];
                }
                const int kg = chunk * 32 + ck;
#pragma unroll
                for (int g = 0; g < 3; g++)
#pragma unroll
                    for (int nt = 0; nt < 2; nt++) {
                        int bn = g * 32 + wn * 16 + nt * 8 + (lane >> 2);
                        unsigned bf[2] = { sW[bn * SW_LD + kg], sW[bn * SW_LD + kg + 4] };
#pragma unroll
                        for (int mt = 0; mt < 2; mt++)
                            mma8(acc[g][mt][nt], af[mt], bf);
                    }
            }
            sr++; if (sr >= 3) sr -= 3;
        }

        if (t < TT - 1) {
            __syncthreads();   // stage0 about to be overwritten by STS below

            // ---- gate math; h into acc[0], next-A stored + STS'd ----
#pragma unroll
            for (int mt = 0; mt < 2; mt++)
#pragma unroll
                for (int half = 0; half < 2; half++) {
                    int q = mt * 2 + half;
                    int n = m0 + wm * 32 + mt * 16 + (lane >> 2) + half * 8;
                    float mnx = pmask[q];
#pragma unroll
                    for (int nt = 0; nt < 2; nt++) {
                        float rr0 = fsig(pir[q][nt].x + acc[0][mt][nt][half * 2]);
                        float rr1 = fsig(pir[q][nt].y + acc[0][mt][nt][half * 2 + 1]);
                        float zz0 = fsig(piz[q][nt].x + acc[1][mt][nt][half * 2]);
                        float zz1 = fsig(piz[q][nt].y + acc[1][mt][nt][half * 2 + 1]);
                        float nn0 = ftanh(pin[q][nt].x + rr0 * (acc[2][mt][nt][half * 2] + bn2[nt].x));
                        float nn1 = ftanh(pin[q][nt].y + rr1 * (acc[2][mt][nt][half * 2 + 1] + bn2[nt].y));
                        float h0 = (1.f - zz0) * nn0 + zz0 * hq[q][nt].x;
                        float h1 = (1.f - zz1) * nn1 + zz1 * hq[q][nt].y;
                        acc[0][mt][nt][half * 2]     = h0;   // park h for outs store
                        acc[0][mt][nt][half * 2 + 1] = h1;
                        float a0 = h0 * mnx + pg[q][nt].x * (1.f - mnx);
                        float a1 = h1 * mnx + pg[q][nt].y * (1.f - mnx);
                        *reinterpret_cast<float2*>(Awr + (size_t)n * HH + cb + nt * 8) =
                            make_float2(a0, a1);
                        hq[q][nt] = make_float2(a0, a1);
                        unsigned ad = sA_u32 +
                            (((wm * 32 + mt * 16 + (lane >> 2) + half * 8) * SA_LD
                              + wn * 16 + nt * 8 + ((lane & 3) << 1)) << 2);
                        asm volatile("st.shared.v2.f32 [%0], {%1,%2};"
                                     :: "r"(ad), "f"(a0), "f"(a1));
                    }
                }

            // ---- arrive (non-blocking) ----
            __syncthreads();
            unsigned tgt = 0u;
            if (tid == 0) {
                __threadfence();
                unsigned g0;
                asm volatile("ld.acquire.gpu.u32 %0, [%1];" : "=r"(g0) : "l"(bgen));
                tgt = g0 + 1u;
                unsigned v = atomicAdd(bcnt, 1u);
                if (v == GSIZE - 1) {
                    *bcnt = 0u;
                    asm volatile("st.release.gpu.u32 [%0], %1;" :: "l"(bgen), "r"(tgt));
                }
            }

            // ---- shadow work: outs stores + next-step prefetch ----
#pragma unroll
            for (int mt = 0; mt < 2; mt++)
#pragma unroll
                for (int half = 0; half < 2; half++) {
                    int n = m0 + wm * 32 + mt * 16 + (lane >> 2) + half * 8;
                    size_t mrow = trow + n;
#pragma unroll
                    for (int nt = 0; nt < 2; nt++)
                        *reinterpret_cast<float2*>(outs + mrow * HH + cb + nt * 8) =
                            make_float2(acc[0][mt][nt][half * 2], acc[0][mt][nt][half * 2 + 1]);
                }
            const size_t trow1 = trow + NB;
            const bool hasnext2 = (t + 2 < TT);
#pragma unroll
            for (int q = 0; q < 4; q++) {
                int n = m0 + wm * 32 + (q >> 1) * 16 + (lane >> 2) + (q & 1) * 8;
                size_t gb = (trow1 + n) * (size_t)H3 + cb;
                pmask[q] = hasnext2 ? masks[trow1 + NB + n] : 0.f;
#pragma unroll
                for (int nt = 0; nt < 2; nt++) {
                    pir[q][nt] = *reinterpret_cast<const float2*>(gi + gb + nt * 8);
                    piz[q][nt] = *reinterpret_cast<const float2*>(gi + gb + HH + nt * 8);
                    pin[q][nt] = *reinterpret_cast<const float2*>(gi + gb + 2 * HH + nt * 8);
                    pg[q][nt] = (cell && hasnext2)
                        ? *reinterpret_cast<const float2*>(
                              ginit + (size_t)(trow1 + NB + n) * HH + cb + nt * 8)
                        : make_float2(0.f, 0.f);
                }
            }

            // ---- wait ----
            if (tid == 0) {
                unsigned cur;
                do { asm volatile("ld.acquire.gpu.u32 %0, [%1];" : "=r"(cur) : "l"(bgen)); }
                while (cur < tgt);
            }
            __syncthreads();
        } else {
            // ---- final step: outs + final hidden state ----
#pragma unroll
            for (int mt = 0; mt < 2; mt++)
#pragma unroll
                for (int half = 0; half < 2; half++) {
                    int q = mt * 2 + half;
                    int n = m0 + wm * 32 + mt * 16 + (lane >> 2) + half * 8;
                    size_t mrow = trow + n;
#pragma unroll
                    for (int nt = 0; nt < 2; nt++) {
                        float rr0 = fsig(pir[q][nt].x + acc[0][mt][nt][half * 2]);
                        float rr1 = fsig(pir[q][nt].y + acc[0][mt][nt][half * 2 + 1]);
                        float zz0 = fsig(piz[q][nt].x + acc[1][mt][nt][half * 2]);
                        float zz1 = fsig(piz[q][nt].y + acc[1][mt][nt][half * 2 + 1]);
                        float nn0 = ftanh(pin[q][nt].x + rr0 * (acc[2][mt][nt][half * 2] + bn2[nt].x));
                        float nn1 = ftanh(pin[q][nt].y + rr1 * (acc[2][mt][nt][half * 2 + 1] + bn2[nt].y));
                        float h0 = (1.f - zz0) * nn0 + zz0 * hq[q][nt].x;
                        float h1 = (1.f - zz1) * nn1 + zz1 * hq[q][nt].y;
                        *reinterpret_cast<float2*>(outs + mrow * HH + cb + nt * 8) =
                            make_float2(h0, h1);
                        *reinterpret_cast<float2*>(hf + (size_t)n * HH + cb + nt * 8) =
                            make_float2(h0, h1);
                    }
                }
        }
    }
}

extern "C" void kernel_launch(void* const* d_in, const int* in_sizes, int n_in,
                              void* d_out, int out_size)
{
    const float* x     = (const float*)d_in[0];
    const float* hxs   = (const float*)d_in[1];
    const float* hys   = (const float*)d_in[2];
    const float* ginit = (const float*)d_in[3];
    const float* masks = (const float*)d_in[4];
    const float* pah   = (const float*)d_in[5];
    const float* wih   = (const float*)d_in[6];
    const float* whh   = (const float*)d_in[7];
    const float* bih   = (const float*)d_in[8];
    const float* bhh   = (const float*)d_in[9];
    const float* wihp  = (const float*)d_in[10];
    const float* whhp  = (const float*)d_in[11];
    const float* bihp  = (const float*)d_in[12];
    const float* bhhp  = (const float*)d_in[13];
    float* out = (float*)d_out;

    gi_gemm_k<<<dim3(12, 256), 256>>>(x, wih, wihp, pah, masks, bih, bihp, bhh, bhhp);

    cudaFuncSetAttribute(scan_k, cudaFuncAttributeMaxDynamicSharedMemorySize, SMEM_SCAN);
    scan_k<<<NCTA, 128, SMEM_SCAN>>>(whh, whhp, masks, ginit, bhh, bhhp, hxs, hys, out);
}

// round 8
// speedup vs baseline: 1.7622x; 1.0622x over previous
#include <cuda_runtime.h>
#include <math.h>

#define TT 128
#define NB 256
#define EE 512
#define AD 8
#define HH 512
#define H3 1536
#define TN (TT*NB)
#define TNH ((size_t)TN*HH)
#define NH (NB*HH)
#define NCTA 128
#define NGROUP 8
#define GSIZE 16

// Scratch (no cudaMalloc allowed)
__device__ float g_gi [(size_t)TN * H3];   // input-side gates, cell 1 (+ b_ih + b_hh[r,z])
__device__ float g_gip[(size_t)TN * H3];   // input-side gates, cell 2
__device__ float g_A [2][2][NH];           // masked hidden state, parity double-buffer
struct __align__(128) Bar { unsigned cnt; unsigned gen; unsigned pad[30]; };
__device__ Bar g_bars[NGROUP];

__device__ __forceinline__ unsigned f2tf(float x) {
    unsigned r;
    asm("cvt.rna.tf32.f32 %0, %1;" : "=r"(r) : "f"(x));
    return r;
}

__device__ __forceinline__ void mma8(float* c, const unsigned* a, const unsigned* b) {
    asm volatile(
        "mma.sync.aligned.m16n8k8.row.col.f32.tf32.tf32.f32 "
        "{%0,%1,%2,%3},{%4,%5,%6,%7},{%8,%9},{%0,%1,%2,%3};"
        : "+f"(c[0]), "+f"(c[1]), "+f"(c[2]), "+f"(c[3])
        : "r"(a[0]), "r"(a[1]), "r"(a[2]), "r"(a[3]), "r"(b[0]), "r"(b[1]));
}

__device__ __forceinline__ float fsig(float x) {
    return 1.f / (1.f + __expf(-x));
}
__device__ __forceinline__ float ftanh(float x) {
    return 1.f - 2.f / (__expf(2.f * x) + 1.f);
}

// ===========================================================================
// GI GEMM (unchanged, passing): g_gi/g_gip with biases folded
// ===========================================================================
__global__ void __launch_bounds__(256) gi_gemm_k(
    const float* __restrict__ x,
    const float* __restrict__ wih,  const float* __restrict__ wihp,
    const float* __restrict__ pah,  const float* __restrict__ masks,
    const float* __restrict__ bih,  const float* __restrict__ bihp,
    const float* __restrict__ bhh,  const float* __restrict__ bhhp)
{
    constexpr int BM = 128, BN = 128, BK = 16, SA = 20;
    constexpr int WRM = 2;
    constexpr int MT = 4, NT = 4, AV = 2, BV = 2;

    __shared__ unsigned sA[2][BM * SA];
    __shared__ unsigned sB[2][BN * SA];

    const int m0 = blockIdx.y * BM;
    const int n0 = blockIdx.x * BN;
    const float* Bg = wih + (size_t)n0 * 520;

    const int tid = threadIdx.x, lane = tid & 31, warp = tid >> 5;
    const int wm = warp % WRM, wn = warp / WRM;

    float acc[MT][NT][4];
    float acc2[MT][NT][4];
#pragma unroll
    for (int i = 0; i < MT; i++)
#pragma unroll
        for (int j = 0; j < NT; j++)
#pragma unroll
            for (int q = 0; q < 4; q++) { acc[i][j][q] = 0.f; acc2[i][j][q] = 0.f; }

    unsigned ra[AV][4], rb[BV][4];

    auto GL = [&](int kc) {
#pragma unroll
        for (int i = 0; i < AV; i++) {
            int s = tid + i * 256; int r = s >> 2; int c = (s & 3) << 2;
            float4 v = *reinterpret_cast<const float4*>(x + (size_t)(m0 + r) * EE + kc * BK + c);
            ra[i][0] = f2tf(v.x); ra[i][1] = f2tf(v.y); ra[i][2] = f2tf(v.z); ra[i][3] = f2tf(v.w);
        }
#pragma unroll
        for (int i = 0; i < BV; i++) {
            int s = tid + i * 256; int r = s >> 2; int c = (s & 3) << 2;
            float4 v = *reinterpret_cast<const float4*>(Bg + (size_t)r * 520 + kc * BK + c);
            rb[i][0] = f2tf(v.x); rb[i][1] = f2tf(v.y); rb[i][2] = f2tf(v.z); rb[i][3] = f2tf(v.w);
        }
    };
    auto SS = [&](int buf) {
#pragma unroll
        for (int i = 0; i < AV; i++) {
            int s = tid + i * 256; int r = s >> 2; int c = (s & 3) << 2;
            *reinterpret_cast<uint4*>(&sA[buf][r * SA + c]) = *reinterpret_cast<uint4*>(ra[i]);
        }
#pragma unroll
        for (int i = 0; i < BV; i++) {
            int s = tid + i * 256; int r = s >> 2; int c = (s & 3) << 2;
            *reinterpret_cast<uint4*>(&sB[buf][r * SA + c]) = *reinterpret_cast<uint4*>(rb[i]);
        }
    };
    auto COMP = [&](int buf) {
#pragma unroll
        for (int k8 = 0; k8 < BK / 8; k8++) {
            unsigned af[MT][4]; unsigned bf[NT][2];
#pragma unroll
            for (int mt = 0; mt < MT; mt++) {
                int r = wm * MT * 16 + mt * 16 + (lane >> 2);
                int c = k8 * 8 + (lane & 3);
                af[mt][0] = sA[buf][r * SA + c];
                af[mt][1] = sA[buf][(r + 8) * SA + c];
                af[mt][2] = sA[buf][r * SA + c + 4];
                af[mt][3] = sA[buf][(r + 8) * SA + c + 4];
            }
#pragma unroll
            for (int nt = 0; nt < NT; nt++) {
                int n = wn * NT * 8 + nt * 8 + (lane >> 2);
                int kk = k8 * 8 + (lane & 3);
                bf[nt][0] = sB[buf][n * SA + kk];
                bf[nt][1] = sB[buf][n * SA + kk + 4];
            }
#pragma unroll
            for (int mt = 0; mt < MT; mt++)
#pragma unroll
                for (int nt = 0; nt < NT; nt++)
                    mma8(acc[mt][nt], af[mt], bf[nt]);
        }
    };

    GL(0); SS(0); __syncthreads();
    constexpr int NKC = EE / BK;
    for (int kc = 0; kc < NKC; kc++) {
        if (kc + 1 < NKC) GL(kc + 1);
        COMP(kc & 1);
        if (kc + 1 < NKC) SS((kc + 1) & 1);
        __syncthreads();
    }

    // Tail: masked prev-action (K=8)
    {
        int s = tid;
        if (s < BM * 2) {
            int r = s >> 1; int c = (s & 1) << 2;
            float4 v = *reinterpret_cast<const float4*>(pah + (size_t)(m0 + r) * AD + c);
            float mk = masks[m0 + r];
            uint4 t4 = { f2tf(v.x * mk), f2tf(v.y * mk), f2tf(v.z * mk), f2tf(v.w * mk) };
            *reinterpret_cast<uint4*>(&sA[0][r * SA + c]) = t4;
        }
        if (s < BN * 2) {
            int n = s >> 1; int c = (s & 1) << 2;
            float4 v = *reinterpret_cast<const float4*>(wih + (size_t)(n0 + n) * 520 + 512 + c);
            uint4 t4 = { f2tf(v.x), f2tf(v.y), f2tf(v.z), f2tf(v.w) };
            *reinterpret_cast<uint4*>(&sB[0][n * SA + c]) = t4;
            float4 w = *reinterpret_cast<const float4*>(wihp + (size_t)(n0 + n) * AD + c);
            uint4 t5 = { f2tf(w.x), f2tf(w.y), f2tf(w.z), f2tf(w.w) };
            *reinterpret_cast<uint4*>(&sB[1][n * SA + c]) = t5;
        }
    }
    __syncthreads();
    {
        unsigned af2[MT][4], b0f[NT][2], b1f[NT][2];
#pragma unroll
        for (int mt = 0; mt < MT; mt++) {
            int r = wm * MT * 16 + mt * 16 + (lane >> 2);
            int c = (lane & 3);
            af2[mt][0] = sA[0][r * SA + c];
            af2[mt][1] = sA[0][(r + 8) * SA + c];
            af2[mt][2] = sA[0][r * SA + c + 4];
            af2[mt][3] = sA[0][(r + 8) * SA + c + 4];
        }
#pragma unroll
        for (int nt = 0; nt < NT; nt++) {
            int n = wn * NT * 8 + nt * 8 + (lane >> 2);
            int kk = (lane & 3);
            b0f[nt][0] = sB[0][n * SA + kk]; b0f[nt][1] = sB[0][n * SA + kk + 4];
            b1f[nt][0] = sB[1][n * SA + kk]; b1f[nt][1] = sB[1][n * SA + kk + 4];
        }
#pragma unroll
        for (int mt = 0; mt < MT; mt++)
#pragma unroll
            for (int nt = 0; nt < NT; nt++) {
                mma8(acc[mt][nt], af2[mt], b0f[nt]);
                mma8(acc2[mt][nt], af2[mt], b1f[nt]);
            }
    }

#pragma unroll
    for (int mt = 0; mt < MT; mt++)
#pragma unroll
        for (int nt = 0; nt < NT; nt++) {
            int r = m0 + wm * MT * 16 + mt * 16 + (lane >> 2);
            int c = n0 + wn * NT * 8 + nt * 8 + ((lane & 3) << 1);
            float hb0 = (c < 1024) ? bhh[c] : 0.f;
            float hb1 = (c < 1024) ? bhh[c + 1] : 0.f;
            float b0 = bih[c] + hb0, b1 = bih[c + 1] + hb1;
            *reinterpret_cast<float2*>(&g_gi[(size_t)r * H3 + c]) =
                make_float2(acc[mt][nt][0] + b0, acc[mt][nt][1] + b1);
            *reinterpret_cast<float2*>(&g_gi[(size_t)(r + 8) * H3 + c]) =
                make_float2(acc[mt][nt][2] + b0, acc[mt][nt][3] + b1);
            float pb0 = (c < 1024) ? bhhp[c] : 0.f;
            float pb1 = (c < 1024) ? bhhp[c + 1] : 0.f;
            float p0 = bihp[c] + pb0, p1 = bihp[c + 1] + pb1;
            *reinterpret_cast<float2*>(&g_gip[(size_t)r * H3 + c]) =
                make_float2(acc2[mt][nt][0] + p0, acc2[mt][nt][1] + p1);
            *reinterpret_cast<float2*>(&g_gip[(size_t)(r + 8) * H3 + c]) =
                make_float2(acc2[mt][nt][2] + p0, acc2[mt][nt][3] + p1);
        }
}

// ===========================================================================
// Persistent scan. 128 CTAs x 256 threads (2 warps/SMSP for latency hiding).
// Warp grid (2 row-halves x 4 col-quarters): each warp M=32, 8 j-cols x 3
// gates. Group barrier + shadow prefetch, own-slice STS, register h.
// ===========================================================================
#define SW_LD 516
#define SA_LD 36
#define SMEM_SCAN ((96*SW_LD + 3*64*SA_LD) * 4)

__global__ void __launch_bounds__(256, 1) scan_k(
    const float* __restrict__ whh, const float* __restrict__ whhp,
    const float* __restrict__ masks, const float* __restrict__ ginit,
    const float* __restrict__ bhh, const float* __restrict__ bhhp,
    const float* __restrict__ hxs, const float* __restrict__ hys,
    float* __restrict__ out)
{
    extern __shared__ unsigned sh[];
    unsigned* sW = sh;                      // 96 x 516 (weights, tf32)
    unsigned* sA = sh + 96 * SW_LD;         // 3 stages x 64 x 36 (A chunks)

    const int bx = blockIdx.x;
    const int p  = bx & 15;                 // j-slice index
    const int j0 = p * 32;
    const int m0 = ((bx >> 4) & 3) * 64;
    const int cell = bx >> 6;
    const int grp = bx >> 4;                // (m,cell) group of 16 CTAs

    const float* W  = cell ? whhp : whh;
    const float* gi = cell ? g_gip : g_gi;
    const float* bh = cell ? bhhp : bhh;
    float* outs = out + (cell ? (TNH + NH) : 0);
    float* hf   = out + (cell ? (2 * TNH + NH) : TNH);
    unsigned* bcnt = &g_bars[grp].cnt;
    unsigned* bgen = &g_bars[grp].gen;

    const int tid = threadIdx.x, lane = tid & 31, warp = tid >> 5;
    const int wm = warp & 1;      // row half (32 rows)
    const int wn = warp >> 1;     // col quarter (8 j-cols x 3 gates)

    // ---- preload weights into SMEM (tf32, RNA) ----
    for (int i = tid; i < 96 * 128; i += 256) {
        int rr = i >> 7, cc = (i & 127) << 2;
        int g = rr >> 5, jj = rr & 31;
        float4 v = *reinterpret_cast<const float4*>(W + (size_t)(g * HH + j0 + jj) * HH + cc);
        unsigned* d = &sW[rr * SW_LD + cc];
        d[0] = f2tf(v.x); d[1] = f2tf(v.y); d[2] = f2tf(v.z); d[3] = f2tf(v.w);
    }

    // ---- init own slice of A(0): global + stage0 SMEM ----
    {
        const float* hsrc = cell ? hys : hxs;
        for (int idx = tid; idx < 64 * 32; idx += 256) {
            int row = idx >> 5, col = idx & 31;
            int n = m0 + row, c = j0 + col;
            float mk = masks[n];
            float v = hsrc[(size_t)n * HH + c] * mk;
            if (cell) v += ginit[(size_t)n * HH + c] * (1.f - mk);
            g_A[cell][0][(size_t)n * HH + c] = v;
            sA[row * SA_LD + col] = __float_as_uint(v);
        }
    }

    const int cb = j0 + wn * 8 + ((lane & 3) << 1);
    const float2 bn2 = *reinterpret_cast<const float2*>(bh + 2 * HH + cb);

    unsigned sA_u32;
    asm("{ .reg .u64 t; cvta.to.shared.u64 t, %1; cvt.u32.u64 %0, t; }"
        : "=r"(sA_u32) : "l"(sA));

    // ---- init barrier (publish A(0) slices) ----
    {
        __syncthreads();
        if (tid == 0) {
            __threadfence();
            unsigned g0;
            asm volatile("ld.acquire.gpu.u32 %0, [%1];" : "=r"(g0) : "l"(bgen));
            unsigned v = atomicAdd(bcnt, 1u);
            if (v == GSIZE - 1) {
                *bcnt = 0u;
                asm volatile("st.release.gpu.u32 [%0], %1;" :: "l"(bgen), "r"(g0 + 1u));
            } else {
                unsigned cur;
                do { asm volatile("ld.acquire.gpu.u32 %0, [%1];" : "=r"(cur) : "l"(bgen)); }
                while (cur < g0 + 1u);
            }
        }
        __syncthreads();
    }

    // ---- register-carried state hq = A(0) fragment (from own stage0) ----
    float2 hq[4];
#pragma unroll
    for (int q = 0; q < 4; q++) {
        int row = wm * 32 + (q >> 1) * 16 + (lane >> 2) + (q & 1) * 8;
        int col = wn * 8 + ((lane & 3) << 1);
        hq[q] = *reinterpret_cast<const float2*>(
            reinterpret_cast<const float*>(sA) + row * SA_LD + col);
    }

    // ---- initial operand prefetch: gi(0), masks(1), ginit(1) ----
    float2 pir[4], piz[4], pin[4], pg[4];
    float pmask[4];
#pragma unroll
    for (int q = 0; q < 4; q++) {
        int n = m0 + wm * 32 + (q >> 1) * 16 + (lane >> 2) + (q & 1) * 8;
        size_t gb = (size_t)n * H3 + cb;
        pmask[q] = masks[NB + n];
        pir[q] = *reinterpret_cast<const float2*>(gi + gb);
        piz[q] = *reinterpret_cast<const float2*>(gi + gb + HH);
        pin[q] = *reinterpret_cast<const float2*>(gi + gb + 2 * HH);
        pg[q] = cell ? *reinterpret_cast<const float2*>(ginit + (size_t)(NB + n) * HH + cb)
                     : make_float2(0.f, 0.f);
    }

    for (int t = 0; t < TT; t++) {
        const int rb = t & 1;
        const float* Ard = g_A[cell][rb];
        float*       Awr = g_A[cell][rb ^ 1];
        const size_t trow = (size_t)t * NB;
        const float* As = Ard + (size_t)m0 * HH;

        auto issue = [&](int chunk, int stg) {
#pragma unroll
            for (int pp = 0; pp < 2; pp++) {
                int s = tid + pp * 256;
                int row = s >> 3;
                int c4 = (s & 7) << 2;
                unsigned d = sA_u32 + ((((stg * 64) + row) * SA_LD + c4) << 2);
                const float* src = As + (size_t)row * HH + chunk * 32 + c4;
                asm volatile("cp.async.cg.shared.global [%0], [%1], 16;" :: "r"(d), "l"(src));
            }
        };

        // chunk p already in stage 0 (STS from previous epilogue / init)
        issue((p + 1) & 15, 1); asm volatile("cp.async.commit_group;");
        issue((p + 2) & 15, 2); asm volatile("cp.async.commit_group;");

        float acc[3][2][4];
#pragma unroll
        for (int g = 0; g < 3; g++)
#pragma unroll
            for (int mt = 0; mt < 2; mt++)
#pragma unroll
                for (int q = 0; q < 4; q++) acc[g][mt][q] = 0.f;

        int sr = 0;
        for (int i = 0; i < 16; i++) {
            const int chunk = (p + i) & 15;
            if (i > 0) {
                if (i < 15) asm volatile("cp.async.wait_group 1;");
                else        asm volatile("cp.async.wait_group 0;");
                __syncthreads();
                if (i <= 13) {
                    int sw = sr + 2; if (sw >= 3) sw -= 3;
                    issue((p + i + 2) & 15, sw);
                    asm volatile("cp.async.commit_group;");
                }
            }
            const unsigned* sab = sA + sr * 64 * SA_LD;
#pragma unroll
            for (int k8 = 0; k8 < 4; k8++) {
                const int ck = k8 * 8 + (lane & 3);
                unsigned af[2][4];
#pragma unroll
                for (int mt = 0; mt < 2; mt++) {
                    int r = wm * 32 + mt * 16 + (lane >> 2);
                    af[mt][0] = sab[r * SA_LD + ck];
                    af[mt][1] = sab[(r + 8) * SA_LD + ck];
                    af[mt][2] = sab[r * SA_LD + ck + 4];
                    af[mt][3] = sab[(r + 8) * SA_LD + ck + 4];
                }
                const int kg = chunk * 32 + ck;
#pragma unroll
                for (int g = 0; g < 3; g++) {
                    int bn = g * 32 + wn * 8 + (lane >> 2);
                    unsigned bf[2] = { sW[bn * SW_LD + kg], sW[bn * SW_LD + kg + 4] };
#pragma unroll
                    for (int mt = 0; mt < 2; mt++)
                        mma8(acc[g][mt], af[mt], bf);
                }
            }
            sr++; if (sr >= 3) sr -= 3;
        }

        if (t < TT - 1) {
            __syncthreads();   // stage0 about to be overwritten by STS below

            // ---- gate math; h parked in acc[0], next-A stored + STS'd ----
#pragma unroll
            for (int mt = 0; mt < 2; mt++)
#pragma unroll
                for (int half = 0; half < 2; half++) {
                    int q = mt * 2 + half;
                    int n = m0 + wm * 32 + mt * 16 + (lane >> 2) + half * 8;
                    float mnx = pmask[q];
                    float rr0 = fsig(pir[q].x + acc[0][mt][half * 2]);
                    float rr1 = fsig(pir[q].y + acc[0][mt][half * 2 + 1]);
                    float zz0 = fsig(piz[q].x + acc[1][mt][half * 2]);
                    float zz1 = fsig(piz[q].y + acc[1][mt][half * 2 + 1]);
                    float nn0 = ftanh(pin[q].x + rr0 * (acc[2][mt][half * 2] + bn2.x));
                    float nn1 = ftanh(pin[q].y + rr1 * (acc[2][mt][half * 2 + 1] + bn2.y));
                    float h0 = (1.f - zz0) * nn0 + zz0 * hq[q].x;
                    float h1 = (1.f - zz1) * nn1 + zz1 * hq[q].y;
                    acc[0][mt][half * 2]     = h0;
                    acc[0][mt][half * 2 + 1] = h1;
                    float a0 = h0 * mnx + pg[q].x * (1.f - mnx);
                    float a1 = h1 * mnx + pg[q].y * (1.f - mnx);
                    *reinterpret_cast<float2*>(Awr + (size_t)n * HH + cb) = make_float2(a0, a1);
                    hq[q] = make_float2(a0, a1);
                    unsigned ad = sA_u32 +
                        (((wm * 32 + mt * 16 + (lane >> 2) + half * 8) * SA_LD
                          + wn * 8 + ((lane & 3) << 1)) << 2);
                    asm volatile("st.shared.v2.f32 [%0], {%1,%2};"
                                 :: "r"(ad), "f"(a0), "f"(a1));
                }

            // ---- arrive (non-blocking) ----
            __syncthreads();
            unsigned tgt = 0u;
            if (tid == 0) {
                __threadfence();
                unsigned g0;
                asm volatile("ld.acquire.gpu.u32 %0, [%1];" : "=r"(g0) : "l"(bgen));
                tgt = g0 + 1u;
                unsigned v = atomicAdd(bcnt, 1u);
                if (v == GSIZE - 1) {
                    *bcnt = 0u;
                    asm volatile("st.release.gpu.u32 [%0], %1;" :: "l"(bgen), "r"(tgt));
                }
            }

            // ---- shadow work: outs stores + next-step prefetch ----
#pragma unroll
            for (int mt = 0; mt < 2; mt++)
#pragma unroll
                for (int half = 0; half < 2; half++) {
                    int n = m0 + wm * 32 + mt * 16 + (lane >> 2) + half * 8;
                    *reinterpret_cast<float2*>(outs + (trow + n) * HH + cb) =
                        make_float2(acc[0][mt][half * 2], acc[0][mt][half * 2 + 1]);
                }
            const size_t trow1 = trow + NB;
            const bool hasnext2 = (t + 2 < TT);
#pragma unroll
            for (int q = 0; q < 4; q++) {
                int n = m0 + wm * 32 + (q >> 1) * 16 + (lane >> 2) + (q & 1) * 8;
                size_t gb = (trow1 + n) * (size_t)H3 + cb;
                pmask[q] = hasnext2 ? masks[trow1 + NB + n] : 0.f;
                pir[q] = *reinterpret_cast<const float2*>(gi + gb);
                piz[q] = *reinterpret_cast<const float2*>(gi + gb + HH);
                pin[q] = *reinterpret_cast<const float2*>(gi + gb + 2 * HH);
                pg[q] = (cell && hasnext2)
                    ? *reinterpret_cast<const float2*>(
                          ginit + (size_t)(trow1 + NB + n) * HH + cb)
                    : make_float2(0.f, 0.f);
            }

            // ---- wait ----
            if (tid == 0) {
                unsigned cur;
                do { asm volatile("ld.acquire.gpu.u32 %0, [%1];" : "=r"(cur) : "l"(bgen)); }
                while (cur < tgt);
            }
            __syncthreads();
        } else {
            // ---- final step: outs + final hidden state ----
#pragma unroll
            for (int mt = 0; mt < 2; mt++)
#pragma unroll
                for (int half = 0; half < 2; half++) {
                    int q = mt * 2 + half;
                    int n = m0 + wm * 32 + mt * 16 + (lane >> 2) + half * 8;
                    size_t mrow = trow + n;
                    float rr0 = fsig(pir[q].x + acc[0][mt][half * 2]);
                    float rr1 = fsig(pir[q].y + acc[0][mt][half * 2 + 1]);
                    float zz0 = fsig(piz[q].x + acc[1][mt][half * 2]);
                    float zz1 = fsig(piz[q].y + acc[1][mt][half * 2 + 1]);
                    float nn0 = ftanh(pin[q].x + rr0 * (acc[2][mt][half * 2] + bn2.x));
                    float nn1 = ftanh(pin[q].y + rr1 * (acc[2][mt][half * 2 + 1] + bn2.y));
                    float h0 = (1.f - zz0) * nn0 + zz0 * hq[q].x;
                    float h1 = (1.f - zz1) * nn1 + zz1 * hq[q].y;
                    *reinterpret_cast<float2*>(outs + mrow * HH + cb) = make_float2(h0, h1);
                    *reinterpret_cast<float2*>(hf + (size_t)n * HH + cb) = make_float2(h0, h1);
                }
        }
    }
}

extern "C" void kernel_launch(void* const* d_in, const int* in_sizes, int n_in,
                              void* d_out, int out_size)
{
    const float* x     = (const float*)d_in[0];
    const float* hxs   = (const float*)d_in[1];
    const float* hys   = (const float*)d_in[2];
    const float* ginit = (const float*)d_in[3];
    const float* masks = (const float*)d_in[4];
    const float* pah   = (const float*)d_in[5];
    const float* wih   = (const float*)d_in[6];
    const float* whh   = (const float*)d_in[7];
    const float* bih   = (const float*)d_in[8];
    const float* bhh   = (const float*)d_in[9];
    const float* wihp  = (const float*)d_in[10];
    const float* whhp  = (const float*)d_in[11];
    const float* bihp  = (const float*)d_in[12];
    const float* bhhp  = (const float*)d_in[13];
    float* out = (float*)d_out;

    gi_gemm_k<<<dim3(12, 256), 256>>>(x, wih, wihp, pah, masks, bih, bihp, bhh, bhhp);

    cudaFuncSetAttribute(scan_k, cudaFuncAttributeMaxDynamicSharedMemorySize, SMEM_SCAN);
    scan_k<<<NCTA, 256, SMEM_SCAN>>>(whh, whhp, masks, ginit, bhh, bhhp, hxs, hys, out);
}